// round 1
// baseline (speedup 1.0000x reference)
#include <cuda_runtime.h>

#define NN 50000
#define EE 800000
#define EN 850000   // EE + NN (self loops)
#define GG 512

// ---------------- scratch (static device globals; no allocation) ----------------
__device__ float g_h [NN * 64];
__device__ float g_xl[NN * 128];
__device__ float g_xr[NN * 128];
__device__ int   g_deg[NN];
__device__ int   g_rowoff[NN + 1];
__device__ int   g_cursor[NN];
__device__ int   g_csrsrc[EN];

// ---------------- embedding gather ----------------
__global__ void embed_k(const int* __restrict__ x, const float* __restrict__ embed) {
    int t = blockIdx.x * blockDim.x + threadIdx.x;
    if (t >= NN * 16) return;
    int n = t >> 4, q = t & 15;
    int row = x[n];
    float4 v = *(const float4*)(embed + row * 64 + q * 4);
    *(float4*)(g_h + n * 64 + q * 4) = v;
}

// ---------------- CSR build (recomputed every call; deterministic enough) ----------------
__global__ void deginit_k() {
    int n = blockIdx.x * blockDim.x + threadIdx.x;
    if (n < NN) g_deg[n] = 1;   // self loop
}

__global__ void hist_k(const int* __restrict__ ei) {
    int e = blockIdx.x * blockDim.x + threadIdx.x;
    if (e >= EE) return;
    atomicAdd(&g_deg[ei[EE + e]], 1);
}

__global__ void scan_k() {
    __shared__ int part[1024];
    const int CHUNK = 49;                 // 1024*49 = 50176 >= NN
    int t = threadIdx.x;
    int s0 = t * CHUNK;
    int sum = 0;
    for (int i = s0; i < s0 + CHUNK && i < NN; i++) sum += g_deg[i];
    part[t] = sum;
    __syncthreads();
    for (int off = 1; off < 1024; off <<= 1) {
        int add = (t >= off) ? part[t - off] : 0;
        __syncthreads();
        part[t] += add;
        __syncthreads();
    }
    int run = (t == 0) ? 0 : part[t - 1];
    for (int i = s0; i < s0 + CHUNK && i < NN; i++) {
        g_rowoff[i] = run;
        g_cursor[i] = run;
        run += g_deg[i];
    }
    if (t == 1023) g_rowoff[NN] = part[1023];
}

__global__ void fill_k(const int* __restrict__ ei) {
    int t = blockIdx.x * blockDim.x + threadIdx.x;
    if (t >= EN) return;
    int s, d;
    if (t < EE) { s = ei[t]; d = ei[EE + t]; }
    else        { s = t - EE; d = s; }         // self loop
    int pos = atomicAdd(&g_cursor[d], 1);
    g_csrsrc[pos] = s;
}

// ---------------- tiled GEMM: C[N x KOUT] = act(A[N x 64] @ W[64 x KOUT] + b) ----------------
template<int KOUT, int TN, bool RELU>
__global__ void gemm_k(const float* A, const float* __restrict__ W,
                       const float* __restrict__ bias, float* C) {
    constexpr int CG = KOUT / 4;            // column groups of 4
    constexpr int NT = TN * KOUT / 1024;    // nodes per thread (=4 for both configs)
    __shared__ float As[TN][64];
    __shared__ float Ws[64 * KOUT];
    __shared__ float bs[KOUT];

    int tid = threadIdx.x;
    int n0  = blockIdx.x * TN;

    for (int f = tid * 4; f < TN * 64; f += 1024) {
        int n = f >> 6, k = f & 63;
        float4 v = make_float4(0.f, 0.f, 0.f, 0.f);
        if (n0 + n < NN) v = *(const float4*)(A + (n0 + n) * 64 + k);
        As[n][k] = v.x; As[n][k + 1] = v.y; As[n][k + 2] = v.z; As[n][k + 3] = v.w;
    }
    for (int f = tid * 4; f < 64 * KOUT; f += 1024)
        *(float4*)(Ws + f) = *(const float4*)(W + f);
    if (tid < KOUT) bs[tid] = bias[tid];
    __syncthreads();

    int cg = tid % CG;
    int ng = tid / CG;

    float acc[NT][4];
#pragma unroll
    for (int i = 0; i < NT; i++) { acc[i][0] = 0.f; acc[i][1] = 0.f; acc[i][2] = 0.f; acc[i][3] = 0.f; }

#pragma unroll 8
    for (int j = 0; j < 64; j++) {
        float4 w4 = *(const float4*)(Ws + j * KOUT + cg * 4);
#pragma unroll
        for (int i = 0; i < NT; i++) {
            float a = As[ng * NT + i][j];
            acc[i][0] += a * w4.x; acc[i][1] += a * w4.y;
            acc[i][2] += a * w4.z; acc[i][3] += a * w4.w;
        }
    }

#pragma unroll
    for (int i = 0; i < NT; i++) {
        int n = n0 + ng * NT + i;
        if (n < NN) {
            float4 o;
            o.x = acc[i][0] + bs[cg * 4 + 0];
            o.y = acc[i][1] + bs[cg * 4 + 1];
            o.z = acc[i][2] + bs[cg * 4 + 2];
            o.w = acc[i][3] + bs[cg * 4 + 3];
            if (RELU) {
                o.x = fmaxf(o.x, 0.f); o.y = fmaxf(o.y, 0.f);
                o.z = fmaxf(o.z, 0.f); o.w = fmaxf(o.w, 0.f);
            }
            *(float4*)(C + n * KOUT + cg * 4) = o;
        }
    }
}

// ---------------- GATv2: one warp per destination node, online softmax, no atomics ----------------
// layout: xl/xr are [N][H*C] = [N][128] with head0 = ch 0..63, head1 = ch 64..127.
// lanes 0..15 own head0 channels (4 each), lanes 16..31 own head1.
__global__ void gat_k(const float* __restrict__ xl, const float* __restrict__ xr,
                      const float* __restrict__ att, const float* __restrict__ bias,
                      float* __restrict__ hout) {
    int gw = (blockIdx.x * blockDim.x + threadIdx.x) >> 5;
    if (gw >= NN) return;
    int lane = threadIdx.x & 31;
    int dst = gw;

    float4 xr4 = *(const float4*)(xr + dst * 128 + lane * 4);
    float4 at4 = *(const float4*)(att + lane * 4);

    int beg = g_rowoff[dst], end = g_rowoff[dst + 1];

    float m = -1e30f, s = 0.f;
    float ax = 0.f, ay = 0.f, az = 0.f, aw = 0.f;

    for (int i = beg; i < end; i++) {
        int src = __ldg(g_csrsrc + i);
        float4 xs = __ldg((const float4*)(xl + src * 128 + lane * 4));
        float vx = xs.x + xr4.x, vy = xs.y + xr4.y;
        float vz = xs.z + xr4.z, vw = xs.w + xr4.w;
        vx = vx > 0.f ? vx : 0.2f * vx;
        vy = vy > 0.f ? vy : 0.2f * vy;
        vz = vz > 0.f ? vz : 0.2f * vz;
        vw = vw > 0.f ? vw : 0.2f * vw;
        float p = vx * at4.x + vy * at4.y + vz * at4.z + vw * at4.w;
        // half-warp butterfly: every lane in a 16-lane half ends with its head's score
        p += __shfl_xor_sync(0xffffffffu, p, 1);
        p += __shfl_xor_sync(0xffffffffu, p, 2);
        p += __shfl_xor_sync(0xffffffffu, p, 4);
        p += __shfl_xor_sync(0xffffffffu, p, 8);
        // branchless online softmax update
        float mn = fmaxf(m, p);
        float r  = __expf(m - mn);
        float w  = __expf(p - mn);
        s  = s  * r + w;
        ax = ax * r + w * xs.x;
        ay = ay * r + w * xs.y;
        az = az * r + w * xs.z;
        aw = aw * r + w * xs.w;
        m = mn;
    }

    float inv = 1.f / s;
    ax *= inv; ay *= inv; az *= inv; aw *= inv;

    // mean over 2 heads: lane l (<16) pairs with lane l+16 (same channel slot)
    float bx = ax + __shfl_xor_sync(0xffffffffu, ax, 16);
    float by = ay + __shfl_xor_sync(0xffffffffu, ay, 16);
    float bz = az + __shfl_xor_sync(0xffffffffu, az, 16);
    float bw = aw + __shfl_xor_sync(0xffffffffu, aw, 16);

    if (lane < 16) {
        float4 b4 = *(const float4*)(bias + lane * 4);
        float4 o = make_float4(0.5f * bx + b4.x, 0.5f * by + b4.y,
                               0.5f * bz + b4.z, 0.5f * bw + b4.w);
        *(float4*)(hout + dst * 64 + lane * 4) = o;
    }
}

// ---------------- output zero + graph segment-sum ----------------
__global__ void zero_k(float* __restrict__ out) {
    int t = blockIdx.x * blockDim.x + threadIdx.x;
    if (t < GG * 128 / 4) {
        *(float4*)(out + t * 4) = make_float4(0.f, 0.f, 0.f, 0.f);
    }
}

__global__ void segsum_k(const int* __restrict__ batch, const float* __restrict__ outn,
                         float* __restrict__ out) {
    int t = blockIdx.x * blockDim.x + threadIdx.x;
    if (t >= NN * 32) return;
    int n = t >> 5, q = t & 31;
    float4 v = *(const float4*)(outn + n * 128 + q * 4);
    int g = batch[n];
    float* p = out + g * 128 + q * 4;
    atomicAdd(p + 0, v.x);
    atomicAdd(p + 1, v.y);
    atomicAdd(p + 2, v.z);
    atomicAdd(p + 3, v.w);
}

// ---------------- launcher ----------------
extern "C" void kernel_launch(void* const* d_in, const int* in_sizes, int n_in,
                              void* d_out, int out_size) {
    const int* x     = (const int*)d_in[0];
    const int* ei    = (const int*)d_in[1];
    const int* batch = (const int*)d_in[2];
    // num_graphs may or may not be materialized as a size-1 input
    int base = (in_sizes[3] == 1) ? 4 : 3;
    const float* embed = (const float*)d_in[base + 0];
    const float* lin_W = (const float*)d_in[base + 1];
    const float* lin_b = (const float*)d_in[base + 2];
    const float* gWl   = (const float*)d_in[base + 3];
    const float* gbl   = (const float*)d_in[base + 4];
    const float* gWr   = (const float*)d_in[base + 5];
    const float* gbr   = (const float*)d_in[base + 6];
    const float* gatt  = (const float*)d_in[base + 7];
    const float* gbias = (const float*)d_in[base + 8];
    const float* rW    = (const float*)d_in[base + 9];
    const float* rb    = (const float*)d_in[base + 10];
    float* out = (float*)d_out;

    void *ph, *pxl, *pxr;
    cudaGetSymbolAddress(&ph,  g_h);
    cudaGetSymbolAddress(&pxl, g_xl);
    cudaGetSymbolAddress(&pxr, g_xr);
    float* h  = (float*)ph;
    float* xl = (float*)pxl;
    float* xr = (float*)pxr;

    // node features from embedding
    embed_k<<<(NN * 16 + 255) / 256, 256>>>(x, embed);

    // CSR by destination (includes self loops)
    deginit_k<<<(NN + 255) / 256, 256>>>();
    hist_k<<<(EE + 255) / 256, 256>>>(ei);
    scan_k<<<1, 1024>>>();
    fill_k<<<(EN + 255) / 256, 256>>>(ei);

    for (int l = 0; l < 3; l++) {
        // h = relu(h @ lin_W + lin_b), in-place (block-local tiles, no cross-block deps)
        gemm_k<64, 64, true><<<(NN + 63) / 64, 256>>>(h, lin_W + l * 64 * 64, lin_b + l * 64, h);
        // xl = h @ Wl + bl ; xr = h @ Wr + br
        gemm_k<128, 32, false><<<(NN + 31) / 32, 256>>>(h, gWl + l * 64 * 128, gbl + l * 128, xl);
        gemm_k<128, 32, false><<<(NN + 31) / 32, 256>>>(h, gWr + l * 64 * 128, gbr + l * 128, xr);
        // GATv2 aggregation -> h
        gat_k<<<(NN + 7) / 8, 256>>>(xl, xr, gatt + l * 128, gbias + l * 64, h);
    }

    // readout (reuse xl as [N,128] temp), then segment-sum into d_out
    gemm_k<128, 32, false><<<(NN + 31) / 32, 256>>>(h, rW, rb, xl);
    zero_k<<<(GG * 128 / 4 + 255) / 256, 256>>>(out);
    segsum_k<<<(NN * 32 + 255) / 256, 256>>>(batch, xl, out);
}